// round 4
// baseline (speedup 1.0000x reference)
#include <cuda_runtime.h>

#define Nn 100000
#define MAXE 3200000
#define Gg 5000
#define BN_EPS 1e-5f

// ---------------- scratch (static device globals) ----------------
__device__ int      g_deg [Nn];
__device__ int      g_row [Nn + 1];
__device__ int      g_cur [Nn];
__device__ int      g_csrc[MAXE];
__device__ float    g_dinv[Nn];
__device__ float    g_ax  [Nn * 20];
__device__ float    g_t   [Nn * 32];    // t2(32) / t3(16)
__device__ float    g_acc1[Nn * 64];
__device__ float    g_h1  [Nn * 64];
__device__ float    g_acc2[Nn * 32];
__device__ float    g_h2  [Nn * 32];
__device__ float    g_acc3[Nn * 16];
__device__ float    g_h3  [Nn * 16];
__device__ float    g_as  [Nn * 8];
__device__ float    g_ad  [Nn * 8];
__device__ float    g_was [16 * 8];
__device__ float    g_wad [16 * 8];
__device__ float    g_pool[Gg * 16];
__device__ float    g_bn  [6 * 64];     // [sum|sumsq] per layer

// ---------------- helpers ----------------
__device__ __forceinline__ void red4(float4* p, float4 v) {
    asm volatile("red.global.add.v4.f32 [%0], {%1,%2,%3,%4};"
                 :: "l"(p), "f"(v.x), "f"(v.y), "f"(v.z), "f"(v.w) : "memory");
}
__device__ __forceinline__ float leaky(float v) { return v > 0.f ? v : 0.2f * v; }

// ---------------- kernels ----------------
__global__ void k_init() {
    int T = gridDim.x * blockDim.x;
    for (int i = blockIdx.x * blockDim.x + threadIdx.x; i < Nn; i += T) {
        g_deg[i] = 0;
        if (i < Gg * 16) g_pool[i] = 0.f;
        if (i < 6 * 64)  g_bn[i] = 0.f;
    }
}

// 4 edges per thread via int4 (E is a multiple of 4 in practice; tail guarded)
__global__ void k_deg(const int* __restrict__ ei, int E) {
    int t = blockIdx.x * blockDim.x + threadIdx.x;
    int i0 = t * 4;
    if (i0 + 3 < E) {
        int4 d4 = *(const int4*)(ei + E + i0);
        atomicAdd(&g_deg[d4.x], 1); atomicAdd(&g_deg[d4.y], 1);
        atomicAdd(&g_deg[d4.z], 1); atomicAdd(&g_deg[d4.w], 1);
    } else {
        for (int i = i0; i < E; i++) atomicAdd(&g_deg[ei[E + i]], 1);
    }
}

// single-block scan over g_deg -> g_row (exclusive), also g_cur = g_row, g_dinv
__global__ void k_scan() {
    __shared__ int sh[1024];
    const int CH = (Nn + 1023) / 1024;
    int t = threadIdx.x;
    int base = t * CH;
    int s = 0;
    for (int i = 0; i < CH; i++) {
        int idx = base + i;
        if (idx < Nn) s += g_deg[idx];
    }
    sh[t] = s;
    __syncthreads();
    for (int off = 1; off < 1024; off <<= 1) {
        int v = (t >= off) ? sh[t - off] : 0;
        __syncthreads();
        sh[t] += v;
        __syncthreads();
    }
    int run = (t == 0) ? 0 : sh[t - 1];
    for (int i = 0; i < CH; i++) {
        int idx = base + i;
        if (idx < Nn) {
            g_row[idx] = run;
            g_cur[idx] = run;
            g_dinv[idx] = rsqrtf((float)(g_deg[idx] + 1));  // +1 self loop
            run += g_deg[idx];
        }
    }
    if (t == 1023) g_row[Nn] = run;
}

__global__ void k_fill(const int* __restrict__ ei, int E) {
    int t = blockIdx.x * blockDim.x + threadIdx.x;
    int i0 = t * 4;
    if (i0 + 3 < E) {
        int4 s4 = *(const int4*)(ei + i0);
        int4 d4 = *(const int4*)(ei + E + i0);
        int p0 = atomicAdd(&g_cur[d4.x], 1);
        int p1 = atomicAdd(&g_cur[d4.y], 1);
        int p2 = atomicAdd(&g_cur[d4.z], 1);
        int p3 = atomicAdd(&g_cur[d4.w], 1);
        g_csrc[p0] = s4.x; g_csrc[p1] = s4.y; g_csrc[p2] = s4.z; g_csrc[p3] = s4.w;
    } else {
        for (int i = i0; i < E; i++) {
            int p = atomicAdd(&g_cur[ei[E + i]], 1);
            g_csrc[p] = ei[i];
        }
    }
}

// out[N,FO] = h[N,FI] @ W[FI,FO] (+ bias if non-null)
template <int FI, int FO, int BLK>
__global__ void k_gemm(const float* __restrict__ h, const float* __restrict__ W,
                       const float* __restrict__ bias, float* __restrict__ out) {
    __shared__ float Ws[FI * FO];
    for (int i = threadIdx.x; i < FI * FO; i += BLK) Ws[i] = W[i];
    __syncthreads();
    const int ROWS = BLK / FO;
    int fo = threadIdx.x % FO;
    int r  = threadIdx.x / FO;
    int node = blockIdx.x * ROWS + r;
    if (node >= Nn) return;
    const float* hr = h + node * FI;
    float acc = bias ? bias[fo] : 0.f;
#pragma unroll
    for (int fi = 0; fi < FI; fi++) acc += hr[fi] * Ws[fi * FO + fo];
    out[node * FO + fo] = acc;
}

// CSR gather: out[d] = sum_{s in adj(d)} t[s]*dinv[s]*dinv[d] + t[d]*dinv[d]^2 (+ bias)
// GRP lanes per node, NV4 active float4 lanes (row = NV4*4 floats, may be < GRP*4)
template <int GRP, int NV4>
__global__ void k_gcn(const float4* __restrict__ t4, const float* __restrict__ b,
                      float4* __restrict__ out4) {
    const int GPW = 32 / GRP;
    int lane = threadIdx.x & 31, warp = threadIdx.x >> 5;
    int grp = lane / GRP, j = lane % GRP;
    int node = (blockIdx.x * (blockDim.x >> 5) + warp) * GPW + grp;
    if (node >= Nn) return;
    bool act = (j < NV4);
    float di = g_dinv[node];
    int r0 = g_row[node], r1 = g_row[node + 1];
    float4 acc = make_float4(0.f, 0.f, 0.f, 0.f);
    if (act) {
        float4 sv = t4[node * NV4 + j];
        float ns = di * di;
        acc = make_float4(sv.x * ns, sv.y * ns, sv.z * ns, sv.w * ns);
    }
#pragma unroll 4
    for (int k = r0; k < r1; k++) {
        int s = g_csrc[k];
        float nm = di * g_dinv[s];
        if (act) {
            float4 v = t4[s * NV4 + j];
            acc.x += v.x * nm; acc.y += v.y * nm; acc.z += v.z * nm; acc.w += v.w * nm;
        }
    }
    if (act) {
        if (b) {
            float4 bb = ((const float4*)b)[j];
            acc.x += bb.x; acc.y += bb.y; acc.z += bb.z; acc.w += bb.w;
        }
        out4[node * NV4 + j] = acc;
    }
}

// per-feature sum and sumsq; total threads must be a multiple of F
template <int F>
__global__ void k_stats(const float* __restrict__ acc, float* __restrict__ stat) {
    int T = gridDim.x * blockDim.x;
    int gtid = blockIdx.x * blockDim.x + threadIdx.x;
    int f = gtid % F;
    float s = 0.f, q = 0.f;
    for (int i = gtid; i < Nn * F; i += T) { float v = acc[i]; s += v; q += v * v; }
    atomicAdd(&stat[f], s);
    atomicAdd(&stat[F + f], q);
}

template <int F>
__global__ void k_bnrelu(const float* __restrict__ acc, const float* __restrict__ stat,
                         const float* __restrict__ g, const float* __restrict__ be,
                         float* __restrict__ out) {
    int i = blockIdx.x * blockDim.x + threadIdx.x;
    if (i >= Nn * F) return;
    int f = i % F;
    const float invn = 1.0f / (float)Nn;
    float mu  = stat[f] * invn;
    float var = stat[F + f] * invn - mu * mu;
    float v = (acc[i] - mu) * rsqrtf(var + BN_EPS) * g[f] + be[f];
    out[i] = fmaxf(v, 0.f);
}

// was[k][h] = sum_c Wg[k][h*16+c] * att_src[h][c]  (and wad likewise). 128 threads.
__global__ void k_prep(const float* __restrict__ Wg, const float* __restrict__ asrc,
                       const float* __restrict__ adst) {
    int t = threadIdx.x;
    int k = t >> 3, h = t & 7;
    float s1 = 0.f, s2 = 0.f;
#pragma unroll
    for (int c = 0; c < 16; c++) {
        float w = Wg[k * 128 + h * 16 + c];
        s1 += w * asrc[h * 16 + c];
        s2 += w * adst[h * 16 + c];
    }
    g_was[k * 8 + h] = s1;
    g_wad[k * 8 + h] = s2;
}

// a_src[n,h] = h3[n] . was[:,h]   (a_dst likewise)
__global__ void k_attdot(const float* __restrict__ h3) {
    int i = blockIdx.x * blockDim.x + threadIdx.x;
    if (i >= Nn * 8) return;
    int node = i >> 3, h = i & 7;
    const float* p = h3 + node * 16;
    float s1 = 0.f, s2 = 0.f;
#pragma unroll
    for (int k = 0; k < 16; k++) {
        float v = p[k];
        s1 += v * g_was[k * 8 + h];
        s2 += v * g_wad[k * 8 + h];
    }
    g_as[i] = s1;
    g_ad[i] = s2;
}

// Fused GAT in h3-space: warp per dst node. Register softmax over incident edges,
// gather 16-dim h3 rows weighted per head, then per-node 8x(16x16) mini-GEMM with Wg,
// head-mean + bg + graph add-pool.
__global__ void k_gat(const float4* __restrict__ h3_4, const float* __restrict__ Wg,
                      const float* __restrict__ bg, const int* __restrict__ batch) {
    __shared__ float Wgs[16 * 128];
    __shared__ float buf[8][8][16];     // [warp][head][k]
    for (int i = threadIdx.x; i < 16 * 128; i += blockDim.x) Wgs[i] = Wg[i];
    __syncthreads();
    int lane = threadIdx.x & 31, warp = threadIdx.x >> 5;
    int d = blockIdx.x * (blockDim.x >> 5) + warp;
    if (d >= Nn) return;
    int h = lane >> 2, j = lane & 3;
    float adh = g_ad[d * 8 + h];
    float asd = g_as[d * 8 + h];
    int r0 = g_row[d], r1 = g_row[d + 1];

    // pass 1: per-head max over incident edges (+self)
    float m = leaky(asd + adh);
#pragma unroll 4
    for (int k = r0; k < r1; k++) {
        int s = g_csrc[k];
        m = fmaxf(m, leaky(g_as[s * 8 + h] + adh));
    }
    // pass 2: sum-exp + weighted h3 accumulation
    float e0 = __expf(leaky(asd + adh) - m);
    float4 xv = h3_4[d * 4 + j];
    float4 acc = make_float4(xv.x * e0, xv.y * e0, xv.z * e0, xv.w * e0);
    float sum = e0;
#pragma unroll 4
    for (int k = r0; k < r1; k++) {
        int s = g_csrc[k];
        float e = __expf(leaky(g_as[s * 8 + h] + adh) - m);
        sum += e;
        float4 v = h3_4[s * 4 + j];
        acc.x += e * v.x; acc.y += e * v.y; acc.z += e * v.z; acc.w += e * v.w;
    }
    float sc = 0.125f / sum;  // alpha-normalize + head-mean in one scale
    buf[warp][h][j * 4 + 0] = acc.x * sc;
    buf[warp][h][j * 4 + 1] = acc.y * sc;
    buf[warp][h][j * 4 + 2] = acc.z * sc;
    buf[warp][h][j * 4 + 3] = acc.w * sc;
    __syncwarp();

    // mini-GEMM: hg[c] = bg[c] + sum_h sum_k buf[h][k] * Wg[k][h*16+c]
    if (lane < 4) {
        float4 hg = ((const float4*)bg)[lane];
#pragma unroll
        for (int hh = 0; hh < 8; hh++) {
#pragma unroll
            for (int k = 0; k < 16; k++) {
                float a = buf[warp][hh][k];
                const float4 w = *(const float4*)&Wgs[k * 128 + hh * 16 + lane * 4];
                hg.x += a * w.x; hg.y += a * w.y; hg.z += a * w.z; hg.w += a * w.w;
            }
        }
        red4(((float4*)g_pool) + batch[d] * 4 + lane, hg);
    }
}

__global__ void k_final(const float* __restrict__ Wf, const float* __restrict__ bf,
                        float* __restrict__ out) {
    int i = blockIdx.x * blockDim.x + threadIdx.x;
    if (i >= Gg * 3) return;
    int gg = i / 3, k = i % 3;
    float s = bf[k];
#pragma unroll
    for (int c = 0; c < 16; c++) s += g_pool[gg * 16 + c] * Wf[c * 3 + k];
    out[i] = s;
}

// ---------------- launch ----------------
static inline void* symaddr(const void* s) { void* p = nullptr; cudaGetSymbolAddress(&p, s); return p; }

extern "C" void kernel_launch(void* const* d_in, const int* in_sizes, int n_in,
                              void* d_out, int out_size) {
    const float* x       = (const float*)d_in[0];
    const int*   ei      = (const int*)  d_in[1];
    const int*   batch   = (const int*)  d_in[2];
    const float* W1 = (const float*)d_in[3],  *b1 = (const float*)d_in[4];
    const float* g1 = (const float*)d_in[5],  *be1= (const float*)d_in[6];
    const float* W2 = (const float*)d_in[7],  *b2 = (const float*)d_in[8];
    const float* g2 = (const float*)d_in[9],  *be2= (const float*)d_in[10];
    const float* W3 = (const float*)d_in[11], *b3 = (const float*)d_in[12];
    const float* g3 = (const float*)d_in[13], *be3= (const float*)d_in[14];
    const float* Wg = (const float*)d_in[15];
    const float* att_src = (const float*)d_in[16];
    const float* att_dst = (const float*)d_in[17];
    const float* bg = (const float*)d_in[18];
    const float* Wf = (const float*)d_in[19], *bf = (const float*)d_in[20];
    float* out = (float*)d_out;
    const int E = in_sizes[1] / 2;

    float* ax   = (float*)symaddr(g_ax);
    float* t    = (float*)symaddr(g_t);
    float* acc1 = (float*)symaddr(g_acc1);
    float* h1   = (float*)symaddr(g_h1);
    float* acc2 = (float*)symaddr(g_acc2);
    float* h2   = (float*)symaddr(g_h2);
    float* acc3 = (float*)symaddr(g_acc3);
    float* h3   = (float*)symaddr(g_h3);
    float* bn   = (float*)symaddr(g_bn);

    const int B = 256;
    // ---- CSR build ----
    k_init<<<(Nn + B - 1) / B, B>>>();
    k_deg<<<(E / 4 + B) / B, B>>>(ei, E);
    k_scan<<<1, 1024>>>();
    k_fill<<<(E / 4 + B) / B, B>>>(ei, E);

    // ---- GCN layer 1: aggregate x (20-dim) first, then GEMM 20->64 ----
    k_gcn<8, 5><<<(Nn + 31) / 32, B>>>((const float4*)x, nullptr, (float4*)ax);
    k_gemm<20, 64, 512><<<(Nn + 7) / 8, 512>>>(ax, W1, b1, acc1);
    k_stats<64><<<512, B>>>(acc1, bn + 0);
    k_bnrelu<64><<<(Nn * 64 + B - 1) / B, B>>>(acc1, bn + 0, g1, be1, h1);

    // ---- GCN layer 2: GEMM 64->32, then aggregate (32-dim) ----
    k_gemm<64, 32, 512><<<(Nn + 15) / 16, 512>>>(h1, W2, nullptr, t);
    k_gcn<8, 8><<<(Nn + 31) / 32, B>>>((const float4*)t, b2, (float4*)acc2);
    k_stats<32><<<512, B>>>(acc2, bn + 128);
    k_bnrelu<32><<<(Nn * 32 + B - 1) / B, B>>>(acc2, bn + 128, g2, be2, h2);

    // ---- GCN layer 3: GEMM 32->16, then aggregate (16-dim) ----
    k_gemm<32, 16, 512><<<(Nn + 31) / 32, 512>>>(h2, W3, nullptr, t);
    k_gcn<4, 4><<<(Nn + 63) / 64, B>>>((const float4*)t, b3, (float4*)acc3);
    k_stats<16><<<512, B>>>(acc3, bn + 256);
    k_bnrelu<16><<<(Nn * 16 + B - 1) / B, B>>>(acc3, bn + 256, g3, be3, h3);

    // ---- GAT in h3-space ----
    k_prep<<<1, 128>>>(Wg, att_src, att_dst);
    k_attdot<<<(Nn * 8 + B - 1) / B, B>>>(h3);
    k_gat<<<(Nn + 7) / 8, B>>>((const float4*)h3, Wg, bg, batch);

    // ---- classifier ----
    k_final<<<(Gg * 3 + B - 1) / B, B>>>(Wf, bf, out);
}

// round 5
// speedup vs baseline: 1.0941x; 1.0941x over previous
#include <cuda_runtime.h>
#include <cuda_fp16.h>

#define Nn 100000
#define MAXE 3200000
#define Gg 5000
#define BN_EPS 1e-5f

// ---------------- scratch (static device globals) ----------------
__device__ int      g_deg [Nn];
__device__ int      g_row [Nn + 1];
__device__ int      g_cur [Nn];
__device__ int      g_csrc[MAXE];
__device__ float    g_dinv[Nn];
__device__ uint4    g_xh  [Nn * 4];     // x' = x*dinv, padded to 32 halfs
__device__ float    g_axp [Nn * 32];    // aggregated x', padded 32 floats
__device__ uint4    g_t2h [Nn * 4];     // t2' = (h1@W2)*dinv, 32 halfs
__device__ uint4    g_t3h [Nn * 2];     // t3' = (h2@W3)*dinv, 16 halfs
__device__ uint2    g_h3h [Nn * 4];     // h3 post-BN, 16 halfs
__device__ float    g_acc1[Nn * 64];
__device__ float    g_h1  [Nn * 64];
__device__ float    g_acc2[Nn * 32];
__device__ float    g_h2  [Nn * 32];
__device__ float    g_acc3[Nn * 16];
__device__ float    g_as  [Nn * 8];
__device__ float    g_ad  [Nn * 8];
__device__ float    g_was [16 * 8];
__device__ float    g_wad [16 * 8];
__device__ float    g_pool[Gg * 16];
__device__ float    g_bn  [6 * 64];     // [sum|sumsq] per layer

// ---------------- helpers ----------------
__device__ __forceinline__ void red4(float4* p, float4 v) {
    asm volatile("red.global.add.v4.f32 [%0], {%1,%2,%3,%4};"
                 :: "l"(p), "f"(v.x), "f"(v.y), "f"(v.z), "f"(v.w) : "memory");
}
__device__ __forceinline__ float leaky(float v) { return v > 0.f ? v : 0.2f * v; }
__device__ __forceinline__ void acc8(float* a, uint4 u) {
    const __half2* h = (const __half2*)&u;
    float2 f0 = __half22float2(h[0]); a[0] += f0.x; a[1] += f0.y;
    float2 f1 = __half22float2(h[1]); a[2] += f1.x; a[3] += f1.y;
    float2 f2 = __half22float2(h[2]); a[4] += f2.x; a[5] += f2.y;
    float2 f3 = __half22float2(h[3]); a[6] += f3.x; a[7] += f3.y;
}

// ---------------- CSR build ----------------
__global__ void k_init() {
    int T = gridDim.x * blockDim.x;
    for (int i = blockIdx.x * blockDim.x + threadIdx.x; i < Nn; i += T) {
        g_deg[i] = 0;
        if (i < Gg * 16) g_pool[i] = 0.f;
        if (i < 6 * 64)  g_bn[i] = 0.f;
    }
}

__global__ void k_deg(const int* __restrict__ ei, int E) {
    int t = blockIdx.x * blockDim.x + threadIdx.x;
    int i0 = t * 4;
    if (i0 + 3 < E) {
        int4 d4 = *(const int4*)(ei + E + i0);
        atomicAdd(&g_deg[d4.x], 1); atomicAdd(&g_deg[d4.y], 1);
        atomicAdd(&g_deg[d4.z], 1); atomicAdd(&g_deg[d4.w], 1);
    } else {
        for (int i = i0; i < E; i++) atomicAdd(&g_deg[ei[E + i]], 1);
    }
}

__global__ void k_scan() {
    __shared__ int sh[1024];
    const int CH = (Nn + 1023) / 1024;
    int t = threadIdx.x;
    int base = t * CH;
    int s = 0;
    for (int i = 0; i < CH; i++) {
        int idx = base + i;
        if (idx < Nn) s += g_deg[idx];
    }
    sh[t] = s;
    __syncthreads();
    for (int off = 1; off < 1024; off <<= 1) {
        int v = (t >= off) ? sh[t - off] : 0;
        __syncthreads();
        sh[t] += v;
        __syncthreads();
    }
    int run = (t == 0) ? 0 : sh[t - 1];
    for (int i = 0; i < CH; i++) {
        int idx = base + i;
        if (idx < Nn) {
            g_row[idx] = run;
            g_cur[idx] = run;
            g_dinv[idx] = rsqrtf((float)(g_deg[idx] + 1));  // +1 self loop
            run += g_deg[idx];
        }
    }
    if (t == 1023) g_row[Nn] = run;
}

__global__ void k_fill(const int* __restrict__ ei, int E) {
    int t = blockIdx.x * blockDim.x + threadIdx.x;
    int i0 = t * 4;
    if (i0 + 3 < E) {
        int4 s4 = *(const int4*)(ei + i0);
        int4 d4 = *(const int4*)(ei + E + i0);
        int p0 = atomicAdd(&g_cur[d4.x], 1);
        int p1 = atomicAdd(&g_cur[d4.y], 1);
        int p2 = atomicAdd(&g_cur[d4.z], 1);
        int p3 = atomicAdd(&g_cur[d4.w], 1);
        g_csrc[p0] = s4.x; g_csrc[p1] = s4.y; g_csrc[p2] = s4.z; g_csrc[p3] = s4.w;
    } else {
        for (int i = i0; i < E; i++) {
            int p = atomicAdd(&g_cur[ei[E + i]], 1);
            g_csrc[p] = ei[i];
        }
    }
}

// x'[n][c] = x[n][c]*dinv[n], zero-padded to 32 halfs
__global__ void k_convx(const float* __restrict__ x) {
    int i = blockIdx.x * blockDim.x + threadIdx.x;
    if (i >= Nn * 32) return;
    int node = i >> 5, c = i & 31;
    float v = (c < 20) ? x[node * 20 + c] * g_dinv[node] : 0.f;
    ((__half*)g_xh)[i] = __float2half_rn(v);
}

// ---------------- GEMM ----------------
// out[N,FO] = h[N,SIN(first FI)] @ W[FI,FO] (+bias); optional *dinv epilogue, half or float out
template <int FI, int FO, int BLK, int SIN, bool SCALE, typename OT>
__global__ void k_gemm(const float* __restrict__ h, const float* __restrict__ W,
                       const float* __restrict__ bias, OT* __restrict__ out) {
    __shared__ float Ws[FI * FO];
    for (int i = threadIdx.x; i < FI * FO; i += BLK) Ws[i] = W[i];
    __syncthreads();
    const int ROWS = BLK / FO;
    int fo = threadIdx.x % FO;
    int r  = threadIdx.x / FO;
    int node = blockIdx.x * ROWS + r;
    if (node >= Nn) return;
    const float* hr = h + node * SIN;
    float acc = bias ? bias[fo] : 0.f;
#pragma unroll
    for (int fi = 0; fi < FI; fi++) acc += hr[fi] * Ws[fi * FO + fo];
    if (SCALE) acc *= g_dinv[node];
    out[node * FO + fo] = (OT)acc;
}

// ---------------- GCN CSR gather (half rows, dinv pre-folded) ----------------
// row = U4 uint4 (U4*8 halfs). out[d] = dinv[d]*(sum_adj row[s] + row[d]) + b  (fp32)
template <int U4>
__global__ void k_gcn(const uint4* __restrict__ rows, const float* __restrict__ b,
                      float4* __restrict__ out4) {
    const int GPW = 32 / U4;
    int lane = threadIdx.x & 31, warp = threadIdx.x >> 5;
    int grp = lane / U4, j = lane % U4;
    int node = (blockIdx.x * (blockDim.x >> 5) + warp) * GPW + grp;
    if (node >= Nn) return;
    float di = g_dinv[node];
    int r0 = g_row[node], r1 = g_row[node + 1];
    float a[8] = {0, 0, 0, 0, 0, 0, 0, 0};
    acc8(a, __ldg(&rows[node * U4 + j]));  // self
    int k = r0;
    for (; k + 3 < r1; k += 4) {
        int s0 = __ldg(&g_csrc[k]);
        int s1 = __ldg(&g_csrc[k + 1]);
        int s2 = __ldg(&g_csrc[k + 2]);
        int s3 = __ldg(&g_csrc[k + 3]);
        uint4 v0 = __ldg(&rows[s0 * U4 + j]);
        uint4 v1 = __ldg(&rows[s1 * U4 + j]);
        uint4 v2 = __ldg(&rows[s2 * U4 + j]);
        uint4 v3 = __ldg(&rows[s3 * U4 + j]);
        acc8(a, v0); acc8(a, v1); acc8(a, v2); acc8(a, v3);
    }
    for (; k < r1; k++) acc8(a, __ldg(&rows[__ldg(&g_csrc[k]) * U4 + j]));
    float4 o0, o1;
    o0.x = a[0] * di; o0.y = a[1] * di; o0.z = a[2] * di; o0.w = a[3] * di;
    o1.x = a[4] * di; o1.y = a[5] * di; o1.z = a[6] * di; o1.w = a[7] * di;
    if (b) {
        float4 b0 = __ldg(&((const float4*)b)[j * 2]);
        float4 b1 = __ldg(&((const float4*)b)[j * 2 + 1]);
        o0.x += b0.x; o0.y += b0.y; o0.z += b0.z; o0.w += b0.w;
        o1.x += b1.x; o1.y += b1.y; o1.z += b1.z; o1.w += b1.w;
    }
    out4[node * (U4 * 2) + j * 2]     = o0;
    out4[node * (U4 * 2) + j * 2 + 1] = o1;
}

// ---------------- BN ----------------
template <int F>
__global__ void k_stats(const float* __restrict__ acc, float* __restrict__ stat) {
    int T = gridDim.x * blockDim.x;
    int gtid = blockIdx.x * blockDim.x + threadIdx.x;
    int f = gtid % F;
    float s = 0.f, q = 0.f;
    for (int i = gtid; i < Nn * F; i += T) { float v = acc[i]; s += v; q += v * v; }
    atomicAdd(&stat[f], s);
    atomicAdd(&stat[F + f], q);
}

template <int F>
__global__ void k_bnrelu(const float* __restrict__ acc, const float* __restrict__ stat,
                         const float* __restrict__ g, const float* __restrict__ be,
                         float* __restrict__ out) {
    int i = blockIdx.x * blockDim.x + threadIdx.x;
    if (i >= Nn * F) return;
    int f = i % F;
    const float invn = 1.0f / (float)Nn;
    float mu  = stat[f] * invn;
    float var = stat[F + f] * invn - mu * mu;
    float v = (acc[i] - mu) * rsqrtf(var + BN_EPS) * g[f] + be[f];
    out[i] = fmaxf(v, 0.f);
}

// was[k][h] = sum_c Wg[k][h*16+c]*att_src[h][c]; wad likewise. 128 threads.
__global__ void k_prep(const float* __restrict__ Wg, const float* __restrict__ asrc,
                       const float* __restrict__ adst) {
    int t = threadIdx.x;
    int k = t >> 3, h = t & 7;
    float s1 = 0.f, s2 = 0.f;
#pragma unroll
    for (int c = 0; c < 16; c++) {
        float w = Wg[k * 128 + h * 16 + c];
        s1 += w * asrc[h * 16 + c];
        s2 += w * adst[h * 16 + c];
    }
    g_was[k * 8 + h] = s1;
    g_wad[k * 8 + h] = s2;
}

// fused BN+ReLU(layer3) + h3->half + attention dots. block=256 -> 16 nodes. Nn%16==0.
__global__ void k_bn3att(const float* __restrict__ acc3, const float* __restrict__ stat,
                         const float* __restrict__ g, const float* __restrict__ be) {
    __shared__ float sv[16][17];
    __shared__ float sw[2][16][8];
    int t = threadIdx.x;
    if (t < 128) { sw[0][t >> 3][t & 7] = g_was[t]; sw[1][t >> 3][t & 7] = g_wad[t]; }
    int node0 = blockIdx.x * 16;
    int nl = t >> 4, f = t & 15;
    const float invn = 1.0f / (float)Nn;
    float mu  = stat[f] * invn;
    float var = stat[16 + f] * invn - mu * mu;
    float v = (acc3[(node0 + nl) * 16 + f] - mu) * rsqrtf(var + BN_EPS) * g[f] + be[f];
    v = fmaxf(v, 0.f);
    sv[nl][f] = v;
    __syncthreads();
    if (t < 64) {
        int n2 = t >> 2, q = t & 3;
        __half2 p0 = __floats2half2_rn(sv[n2][q * 4 + 0], sv[n2][q * 4 + 1]);
        __half2 p1 = __floats2half2_rn(sv[n2][q * 4 + 2], sv[n2][q * 4 + 3]);
        uint2 u;
        u.x = *(unsigned*)&p0;
        u.y = *(unsigned*)&p1;
        g_h3h[(node0 + n2) * 4 + q] = u;
    }
    if (t < 128) {
        int n3 = t >> 3, h = t & 7;
        float s1 = 0.f, s2 = 0.f;
#pragma unroll
        for (int k = 0; k < 16; k++) {
            float hv = sv[n3][k];
            s1 += hv * sw[0][k][h];
            s2 += hv * sw[1][k][h];
        }
        g_as[(node0 + n3) * 8 + h] = s1;
        g_ad[(node0 + n3) * 8 + h] = s2;
    }
}

// ---------------- fused GAT (single-pass online softmax) ----------------
__device__ __forceinline__ void gat_step(float l, uint2 u, float& m, float& sum, float4& acc) {
    float2 f0 = __half22float2(*(const __half2*)&u.x);
    float2 f1 = __half22float2(*(const __half2*)&u.y);
    float d = l - m;
    float e = __expf(-fabsf(d));
    if (d <= 0.f) {
        sum += e;
        acc.x += e * f0.x; acc.y += e * f0.y; acc.z += e * f1.x; acc.w += e * f1.y;
    } else {
        sum = sum * e + 1.f;
        acc.x = acc.x * e + f0.x; acc.y = acc.y * e + f0.y;
        acc.z = acc.z * e + f1.x; acc.w = acc.w * e + f1.y;
        m = l;
    }
}

__global__ void k_gat(const float* __restrict__ Wg, const float* __restrict__ bg,
                      const int* __restrict__ batch) {
    __shared__ float Wgs[16 * 128];
    __shared__ float buf[8][8][16];     // [warp][head][k]
    for (int i = threadIdx.x; i < 16 * 128; i += blockDim.x) Wgs[i] = Wg[i];
    __syncthreads();
    int lane = threadIdx.x & 31, warp = threadIdx.x >> 5;
    int d = blockIdx.x * (blockDim.x >> 5) + warp;
    if (d >= Nn) return;
    int h = lane >> 2, j = lane & 3;
    float adh = g_ad[d * 8 + h];
    int r0 = g_row[d], r1 = g_row[d + 1];

    // init with self edge
    float m = leaky(g_as[d * 8 + h] + adh);
    float sum = 1.f;
    uint2 su = __ldg(&g_h3h[d * 4 + j]);
    float2 sf0 = __half22float2(*(const __half2*)&su.x);
    float2 sf1 = __half22float2(*(const __half2*)&su.y);
    float4 acc = make_float4(sf0.x, sf0.y, sf1.x, sf1.y);

    int k = r0;
    for (; k + 3 < r1; k += 4) {
        int s0 = __ldg(&g_csrc[k]);
        int s1 = __ldg(&g_csrc[k + 1]);
        int s2 = __ldg(&g_csrc[k + 2]);
        int s3 = __ldg(&g_csrc[k + 3]);
        float l0 = leaky(__ldg(&g_as[s0 * 8 + h]) + adh);
        float l1 = leaky(__ldg(&g_as[s1 * 8 + h]) + adh);
        float l2 = leaky(__ldg(&g_as[s2 * 8 + h]) + adh);
        float l3 = leaky(__ldg(&g_as[s3 * 8 + h]) + adh);
        uint2 u0 = __ldg(&g_h3h[s0 * 4 + j]);
        uint2 u1 = __ldg(&g_h3h[s1 * 4 + j]);
        uint2 u2 = __ldg(&g_h3h[s2 * 4 + j]);
        uint2 u3 = __ldg(&g_h3h[s3 * 4 + j]);
        gat_step(l0, u0, m, sum, acc);
        gat_step(l1, u1, m, sum, acc);
        gat_step(l2, u2, m, sum, acc);
        gat_step(l3, u3, m, sum, acc);
    }
    for (; k < r1; k++) {
        int s = __ldg(&g_csrc[k]);
        float l = leaky(__ldg(&g_as[s * 8 + h]) + adh);
        gat_step(l, __ldg(&g_h3h[s * 4 + j]), m, sum, acc);
    }
    float sc = 0.125f / sum;  // alpha-normalize + head-mean
    buf[warp][h][j * 4 + 0] = acc.x * sc;
    buf[warp][h][j * 4 + 1] = acc.y * sc;
    buf[warp][h][j * 4 + 2] = acc.z * sc;
    buf[warp][h][j * 4 + 3] = acc.w * sc;
    __syncwarp();

    // mini-GEMM: hg[c] = bg[c] + sum_h sum_k buf[h][k]*Wg[k][h*16+c]; then pool
    if (lane < 4) {
        float4 hg = ((const float4*)bg)[lane];
#pragma unroll
        for (int hh = 0; hh < 8; hh++) {
#pragma unroll
            for (int kk = 0; kk < 16; kk++) {
                float a = buf[warp][hh][kk];
                const float4 w = *(const float4*)&Wgs[kk * 128 + hh * 16 + lane * 4];
                hg.x += a * w.x; hg.y += a * w.y; hg.z += a * w.z; hg.w += a * w.w;
            }
        }
        red4(((float4*)g_pool) + batch[d] * 4 + lane, hg);
    }
}

__global__ void k_final(const float* __restrict__ Wf, const float* __restrict__ bf,
                        float* __restrict__ out) {
    int i = blockIdx.x * blockDim.x + threadIdx.x;
    if (i >= Gg * 3) return;
    int gg = i / 3, k = i % 3;
    float s = bf[k];
#pragma unroll
    for (int c = 0; c < 16; c++) s += g_pool[gg * 16 + c] * Wf[c * 3 + k];
    out[i] = s;
}

// ---------------- launch ----------------
static inline void* symaddr(const void* s) { void* p = nullptr; cudaGetSymbolAddress(&p, s); return p; }

extern "C" void kernel_launch(void* const* d_in, const int* in_sizes, int n_in,
                              void* d_out, int out_size) {
    const float* x       = (const float*)d_in[0];
    const int*   ei      = (const int*)  d_in[1];
    const int*   batch   = (const int*)  d_in[2];
    const float* W1 = (const float*)d_in[3],  *b1 = (const float*)d_in[4];
    const float* g1 = (const float*)d_in[5],  *be1= (const float*)d_in[6];
    const float* W2 = (const float*)d_in[7],  *b2 = (const float*)d_in[8];
    const float* g2 = (const float*)d_in[9],  *be2= (const float*)d_in[10];
    const float* W3 = (const float*)d_in[11], *b3 = (const float*)d_in[12];
    const float* g3 = (const float*)d_in[13], *be3= (const float*)d_in[14];
    const float* Wg = (const float*)d_in[15];
    const float* att_src = (const float*)d_in[16];
    const float* att_dst = (const float*)d_in[17];
    const float* bg = (const float*)d_in[18];
    const float* Wf = (const float*)d_in[19], *bf = (const float*)d_in[20];
    float* out = (float*)d_out;
    const int E = in_sizes[1] / 2;

    float* axp  = (float*)symaddr(g_axp);
    float* acc1 = (float*)symaddr(g_acc1);
    float* h1   = (float*)symaddr(g_h1);
    float* acc2 = (float*)symaddr(g_acc2);
    float* h2   = (float*)symaddr(g_h2);
    float* acc3 = (float*)symaddr(g_acc3);
    float* bn   = (float*)symaddr(g_bn);
    uint4* xh   = (uint4*)symaddr(g_xh);
    uint4* t2h  = (uint4*)symaddr(g_t2h);
    uint4* t3h  = (uint4*)symaddr(g_t3h);

    const int B = 256;
    // ---- CSR build ----
    k_init<<<(Nn + B - 1) / B, B>>>();
    k_deg<<<(E / 4 + B) / B, B>>>(ei, E);
    k_scan<<<1, 1024>>>();
    k_fill<<<(E / 4 + B) / B, B>>>(ei, E);
    k_convx<<<(Nn * 32 + B - 1) / B, B>>>(x);

    // ---- GCN layer 1: aggregate x' (half), GEMM 20->64 ----
    k_gcn<4><<<(Nn + 63) / 64, B>>>(xh, nullptr, (float4*)axp);
    k_gemm<20, 64, 512, 32, false, float><<<(Nn + 7) / 8, 512>>>(axp, W1, b1, acc1);
    k_stats<64><<<512, B>>>(acc1, bn + 0);
    k_bnrelu<64><<<(Nn * 64 + B - 1) / B, B>>>(acc1, bn + 0, g1, be1, h1);

    // ---- GCN layer 2: GEMM 64->32 (half, *dinv), aggregate ----
    k_gemm<64, 32, 512, 64, true, __half><<<(Nn + 15) / 16, 512>>>(h1, W2, nullptr, (__half*)t2h);
    k_gcn<4><<<(Nn + 63) / 64, B>>>(t2h, b2, (float4*)acc2);
    k_stats<32><<<512, B>>>(acc2, bn + 128);
    k_bnrelu<32><<<(Nn * 32 + B - 1) / B, B>>>(acc2, bn + 128, g2, be2, h2);

    // ---- GCN layer 3: GEMM 32->16 (half, *dinv), aggregate ----
    k_gemm<32, 16, 512, 32, true, __half><<<(Nn + 31) / 32, 512>>>(h2, W3, nullptr, (__half*)t3h);
    k_gcn<2><<<(Nn + 127) / 128, B>>>(t3h, b3, (float4*)acc3);
    k_stats<16><<<512, B>>>(acc3, bn + 256);

    // ---- BN3 + attention dots fused, then single-pass GAT ----
    k_prep<<<1, 128>>>(Wg, att_src, att_dst);
    k_bn3att<<<Nn / 16, B>>>(acc3, bn + 256, g3, be3);
    k_gat<<<(Nn + 7) / 8, B>>>(Wg, bg, batch);

    // ---- classifier ----
    k_final<<<(Gg * 3 + B - 1) / B, B>>>(Wf, bf, out);
}

// round 6
// speedup vs baseline: 1.4696x; 1.3432x over previous
#include <cuda_runtime.h>
#include <cuda_fp16.h>

#define Nn 100000
#define MAXE 3200000
#define Gg 5000
#define BN_EPS 1e-5f

// ---------------- scratch (static device globals) ----------------
__device__ int      g_deg [Nn];
__device__ int      g_row [Nn + 1];
__device__ int      g_cur [Nn];
__device__ int      g_csrc[MAXE];
__device__ float    g_dinv[Nn];
__device__ uint4    g_xh  [Nn * 4];     // x' = x*dinv, padded to 32 halfs
__device__ float    g_axp [Nn * 32];    // aggregated x', padded 32 floats
__device__ uint4    g_t2h [Nn * 4];     // t2' = bnrelu(acc1)@W2*dinv, 32 halfs
__device__ uint4    g_t3h [Nn * 2];     // t3' = bnrelu(acc2)@W3*dinv, 16 halfs
__device__ uint2    g_h3h [Nn * 4];     // h3 post-BN, 16 halfs
__device__ float    g_acc1[Nn * 64];
__device__ float    g_acc2[Nn * 32];
__device__ float    g_acc3[Nn * 16];
__device__ float    g_as  [Nn * 8];
__device__ float    g_ad  [Nn * 8];
__device__ float    g_was [16 * 8];
__device__ float    g_wad [16 * 8];
__device__ float    g_pool[Gg * 16];
__device__ float    g_bn  [6 * 64];     // [sum|sumsq] per layer: L1@0, L2@128, L3@256

// ---------------- helpers ----------------
__device__ __forceinline__ void red4(float4* p, float4 v) {
    asm volatile("red.global.add.v4.f32 [%0], {%1,%2,%3,%4};"
                 :: "l"(p), "f"(v.x), "f"(v.y), "f"(v.z), "f"(v.w) : "memory");
}
__device__ __forceinline__ float leaky(float v) { return v > 0.f ? v : 0.2f * v; }
__device__ __forceinline__ void acc8(float* a, uint4 u) {
    const __half2* h = (const __half2*)&u;
    float2 f0 = __half22float2(h[0]); a[0] += f0.x; a[1] += f0.y;
    float2 f1 = __half22float2(h[1]); a[2] += f1.x; a[3] += f1.y;
    float2 f2 = __half22float2(h[2]); a[4] += f2.x; a[5] += f2.y;
    float2 f3 = __half22float2(h[3]); a[6] += f3.x; a[7] += f3.y;
}

// ---------------- CSR build ----------------
__global__ void k_init() {
    int T = gridDim.x * blockDim.x;
    for (int i = blockIdx.x * blockDim.x + threadIdx.x; i < Nn; i += T) {
        g_deg[i] = 0;
        if (i < Gg * 16) g_pool[i] = 0.f;
        if (i < 6 * 64)  g_bn[i] = 0.f;
    }
}

__global__ void k_deg(const int* __restrict__ ei, int E) {
    int t = blockIdx.x * blockDim.x + threadIdx.x;
    int i0 = t * 4;
    if (i0 + 3 < E) {
        int4 d4 = *(const int4*)(ei + E + i0);
        atomicAdd(&g_deg[d4.x], 1); atomicAdd(&g_deg[d4.y], 1);
        atomicAdd(&g_deg[d4.z], 1); atomicAdd(&g_deg[d4.w], 1);
    } else {
        for (int i = i0; i < E; i++) atomicAdd(&g_deg[ei[E + i]], 1);
    }
}

// single-block coalesced scan over g_deg -> g_row (exclusive); g_cur, g_dinv
__global__ void k_scan() {
    __shared__ int wsum[32];
    int t = threadIdx.x, lane = t & 31, w = t >> 5;
    int carry = 0;
    for (int base = 0; base < Nn; base += 1024) {
        int idx = base + t;
        int v = (idx < Nn) ? g_deg[idx] : 0;
        int x = v;
#pragma unroll
        for (int off = 1; off < 32; off <<= 1) {
            int y = __shfl_up_sync(~0u, x, off);
            if (lane >= off) x += y;
        }
        if (lane == 31) wsum[w] = x;
        __syncthreads();
        if (w == 0) {
            int s = wsum[lane];
#pragma unroll
            for (int off = 1; off < 32; off <<= 1) {
                int y = __shfl_up_sync(~0u, s, off);
                if (lane >= off) s += y;
            }
            wsum[lane] = s;
        }
        __syncthreads();
        int woff = (w == 0) ? 0 : wsum[w - 1];
        int excl = carry + woff + x - v;
        if (idx < Nn) {
            g_row[idx] = excl;
            g_cur[idx] = excl;
            g_dinv[idx] = rsqrtf((float)(v + 1));  // +1 self loop
        }
        int tot = wsum[31];
        __syncthreads();
        carry += tot;
    }
    if (t == 0) g_row[Nn] = carry;
}

__global__ void k_fill(const int* __restrict__ ei, int E) {
    int t = blockIdx.x * blockDim.x + threadIdx.x;
    int i0 = t * 4;
    if (i0 + 3 < E) {
        int4 s4 = *(const int4*)(ei + i0);
        int4 d4 = *(const int4*)(ei + E + i0);
        int p0 = atomicAdd(&g_cur[d4.x], 1);
        int p1 = atomicAdd(&g_cur[d4.y], 1);
        int p2 = atomicAdd(&g_cur[d4.z], 1);
        int p3 = atomicAdd(&g_cur[d4.w], 1);
        g_csrc[p0] = s4.x; g_csrc[p1] = s4.y; g_csrc[p2] = s4.z; g_csrc[p3] = s4.w;
    } else {
        for (int i = i0; i < E; i++) {
            int p = atomicAdd(&g_cur[ei[E + i]], 1);
            g_csrc[p] = ei[i];
        }
    }
}

// x'[n][c] = x[n][c]*dinv[n], zero-padded to 32 halfs
__global__ void k_convx(const float* __restrict__ x) {
    int i = blockIdx.x * blockDim.x + threadIdx.x;
    if (i >= Nn * 32) return;
    int node = i >> 5, c = i & 31;
    float v = (c < 20) ? x[node * 20 + c] * g_dinv[node] : 0.f;
    ((__half*)g_xh)[i] = __float2half_rn(v);
}

// ---------------- GCN CSR gather (half rows, dinv pre-folded, pipelined) ----------------
// row = U4 uint4 (U4*8 halfs). out[d] = dinv[d]*(sum_adj row[s] + row[d]) + b  (fp32)
// STATS: block-reduced per-feature sum/sumsq -> stat[0..F), stat[F..2F)
template <int U4, bool STATS>
__global__ void k_gcn(const uint4* __restrict__ rows, const float* __restrict__ b,
                      float4* __restrict__ out4, float* __restrict__ stat) {
    const int F = U4 * 8;
    __shared__ float ss[F], sq[F];
    if (STATS) {
        if (threadIdx.x < F) { ss[threadIdx.x] = 0.f; sq[threadIdx.x] = 0.f; }
        __syncthreads();
    }
    const int GPW = 32 / U4;
    int lane = threadIdx.x & 31, warp = threadIdx.x >> 5;
    int grp = lane / U4, j = lane % U4;
    int node = (blockIdx.x * (blockDim.x >> 5) + warp) * GPW + grp;
    bool act = node < Nn;
    float a[8] = {0, 0, 0, 0, 0, 0, 0, 0};
    float di = 0.f;
    int r0 = 0, r1 = 0;
    if (act) {
        di = g_dinv[node];
        r0 = g_row[node];
        r1 = g_row[node + 1];
        acc8(a, __ldg(&rows[node * U4 + j]));  // self
    }
    int k = r0;
    if (k + 3 < r1) {
        int i0 = __ldg(&g_csrc[k]), i1 = __ldg(&g_csrc[k + 1]);
        int i2 = __ldg(&g_csrc[k + 2]), i3 = __ldg(&g_csrc[k + 3]);
        while (true) {
            int kn = k + 4;
            bool more = (kn + 3 < r1);
            int n0, n1, n2, n3;
            if (more) {
                n0 = __ldg(&g_csrc[kn]);     n1 = __ldg(&g_csrc[kn + 1]);
                n2 = __ldg(&g_csrc[kn + 2]); n3 = __ldg(&g_csrc[kn + 3]);
            }
            uint4 v0 = __ldg(&rows[i0 * U4 + j]);
            uint4 v1 = __ldg(&rows[i1 * U4 + j]);
            uint4 v2 = __ldg(&rows[i2 * U4 + j]);
            uint4 v3 = __ldg(&rows[i3 * U4 + j]);
            acc8(a, v0); acc8(a, v1); acc8(a, v2); acc8(a, v3);
            k = kn;
            if (!more) break;
            i0 = n0; i1 = n1; i2 = n2; i3 = n3;
        }
    }
    for (; k < r1; k++) acc8(a, __ldg(&rows[__ldg(&g_csrc[k]) * U4 + j]));

    float o[8];
    float4 b0 = b ? __ldg(&((const float4*)b)[j * 2])     : make_float4(0, 0, 0, 0);
    float4 b1 = b ? __ldg(&((const float4*)b)[j * 2 + 1]) : make_float4(0, 0, 0, 0);
#pragma unroll
    for (int c = 0; c < 8; c++) {
        float bb = (c < 4) ? (&b0.x)[c] : (&b1.x)[c - 4];
        o[c] = act ? (a[c] * di + bb) : 0.f;
    }
    if (act) {
        float4 w0 = make_float4(o[0], o[1], o[2], o[3]);
        float4 w1 = make_float4(o[4], o[5], o[6], o[7]);
        out4[node * (U4 * 2) + j * 2]     = w0;
        out4[node * (U4 * 2) + j * 2 + 1] = w1;
    }
    if (STATS) {
        // butterfly-reduce over the GPW groups (lanes with same j)
        float q[8];
#pragma unroll
        for (int c = 0; c < 8; c++) q[c] = o[c] * o[c];
#pragma unroll
        for (int off = U4; off < 32; off <<= 1) {
#pragma unroll
            for (int c = 0; c < 8; c++) {
                o[c] += __shfl_xor_sync(~0u, o[c], off);
                q[c] += __shfl_xor_sync(~0u, q[c], off);
            }
        }
        if (grp == 0) {
#pragma unroll
            for (int c = 0; c < 8; c++) {
                atomicAdd(&ss[j * 8 + c], o[c]);
                atomicAdd(&sq[j * 8 + c], q[c]);
            }
        }
        __syncthreads();
        if (threadIdx.x < F) {
            atomicAdd(&stat[threadIdx.x], ss[threadIdx.x]);
            atomicAdd(&stat[F + threadIdx.x], sq[threadIdx.x]);
        }
    }
}

// ---------------- GEMM layer 1: axp(20 of 32) @ W1 + b1 -> acc1, with stats ----------------
__global__ void k_gemm1(const float* __restrict__ h, const float* __restrict__ W,
                        const float* __restrict__ bias, float* __restrict__ out,
                        float* __restrict__ stat) {
    __shared__ float Ws[20 * 64];
    __shared__ float ss[64], sq[64];
    int tid = threadIdx.x;
    for (int i = tid; i < 20 * 64; i += 512) Ws[i] = W[i];
    if (tid < 64) { ss[tid] = 0.f; sq[tid] = 0.f; }
    __syncthreads();
    int fo = tid & 63, r = tid >> 6;
    int node = blockIdx.x * 8 + r;                 // 100000/8 = 12500 exact
    const float* hr = h + node * 32;
    float a = bias[fo];
#pragma unroll
    for (int fi = 0; fi < 20; fi++) a += hr[fi] * Ws[fi * 64 + fo];
    out[node * 64 + fo] = a;
    atomicAdd(&ss[fo], a);
    atomicAdd(&sq[fo], a * a);
    __syncthreads();
    if (tid < 64) {
        atomicAdd(&stat[tid], ss[tid]);
        atomicAdd(&stat[64 + tid], sq[tid]);
    }
}

// ---------------- fused BN+ReLU + GEMM + *dinv -> half ----------------
template <int FI, int FO>
__global__ void k_gemmbn(const float* __restrict__ acc, const float* __restrict__ stat,
                         const float* __restrict__ g, const float* __restrict__ be,
                         const float* __restrict__ W, __half* __restrict__ out) {
    const int BLK = 512;
    const int ROWS = BLK / FO;
    __shared__ float Ws[FI * FO];
    __shared__ float Hs[ROWS * FI];
    __shared__ float sc[FI], sh[FI];
    int tid = threadIdx.x;
    for (int i = tid; i < FI * FO; i += BLK) Ws[i] = W[i];
    if (tid < FI) {
        const float invn = 1.0f / (float)Nn;
        float mu  = stat[tid] * invn;
        float var = stat[FI + tid] * invn - mu * mu;
        float kk  = g[tid] * rsqrtf(var + BN_EPS);
        sc[tid] = kk;
        sh[tid] = be[tid] - mu * kk;
    }
    __syncthreads();
    int node0 = blockIdx.x * ROWS;
    for (int i = tid; i < ROWS * FI; i += BLK) {
        int r = i / FI, f = i % FI;
        Hs[i] = fmaxf(acc[(node0 + r) * FI + f] * sc[f] + sh[f], 0.f);
    }
    __syncthreads();
    int fo = tid % FO, r = tid / FO;
    int node = node0 + r;
    float a = 0.f;
#pragma unroll
    for (int fi = 0; fi < FI; fi++) a += Hs[r * FI + fi] * Ws[fi * FO + fo];
    a *= g_dinv[node];
    out[node * FO + fo] = __float2half_rn(a);
}

// was[k][h] = sum_c Wg[k][h*16+c]*att_src[h][c]; wad likewise. 128 threads.
__global__ void k_prep(const float* __restrict__ Wg, const float* __restrict__ asrc,
                       const float* __restrict__ adst) {
    int t = threadIdx.x;
    int k = t >> 3, h = t & 7;
    float s1 = 0.f, s2 = 0.f;
#pragma unroll
    for (int c = 0; c < 16; c++) {
        float w = Wg[k * 128 + h * 16 + c];
        s1 += w * asrc[h * 16 + c];
        s2 += w * adst[h * 16 + c];
    }
    g_was[k * 8 + h] = s1;
    g_wad[k * 8 + h] = s2;
}

// fused BN+ReLU(layer3) + h3->half + attention dots. block=256 -> 16 nodes. Nn%16==0.
__global__ void k_bn3att(const float* __restrict__ acc3, const float* __restrict__ stat,
                         const float* __restrict__ g, const float* __restrict__ be) {
    __shared__ float sv[16][17];
    __shared__ float sw[2][16][8];
    int t = threadIdx.x;
    if (t < 128) { sw[0][t >> 3][t & 7] = g_was[t]; sw[1][t >> 3][t & 7] = g_wad[t]; }
    int node0 = blockIdx.x * 16;
    int nl = t >> 4, f = t & 15;
    const float invn = 1.0f / (float)Nn;
    float mu  = stat[f] * invn;
    float var = stat[16 + f] * invn - mu * mu;
    float v = (acc3[(node0 + nl) * 16 + f] - mu) * rsqrtf(var + BN_EPS) * g[f] + be[f];
    v = fmaxf(v, 0.f);
    sv[nl][f] = v;
    __syncthreads();
    if (t < 64) {
        int n2 = t >> 2, q = t & 3;
        __half2 p0 = __floats2half2_rn(sv[n2][q * 4 + 0], sv[n2][q * 4 + 1]);
        __half2 p1 = __floats2half2_rn(sv[n2][q * 4 + 2], sv[n2][q * 4 + 3]);
        uint2 u;
        u.x = *(unsigned*)&p0;
        u.y = *(unsigned*)&p1;
        g_h3h[(node0 + n2) * 4 + q] = u;
    }
    if (t < 128) {
        int n3 = t >> 3, h = t & 7;
        float s1 = 0.f, s2 = 0.f;
#pragma unroll
        for (int k = 0; k < 16; k++) {
            float hv = sv[n3][k];
            s1 += hv * sw[0][k][h];
            s2 += hv * sw[1][k][h];
        }
        g_as[(node0 + n3) * 8 + h] = s1;
        g_ad[(node0 + n3) * 8 + h] = s2;
    }
}

// ---------------- fused GAT (single-pass online softmax, pipelined) ----------------
__device__ __forceinline__ void gat_step(float l, uint2 u, float& m, float& sum, float4& acc) {
    float2 f0 = __half22float2(*(const __half2*)&u.x);
    float2 f1 = __half22float2(*(const __half2*)&u.y);
    float d = l - m;
    float e = __expf(-fabsf(d));
    if (d <= 0.f) {
        sum += e;
        acc.x += e * f0.x; acc.y += e * f0.y; acc.z += e * f1.x; acc.w += e * f1.y;
    } else {
        sum = sum * e + 1.f;
        acc.x = acc.x * e + f0.x; acc.y = acc.y * e + f0.y;
        acc.z = acc.z * e + f1.x; acc.w = acc.w * e + f1.y;
        m = l;
    }
}

__global__ void k_gat(const float* __restrict__ Wg, const float* __restrict__ bg,
                      const int* __restrict__ batch) {
    __shared__ float Wgs[16 * 128];
    __shared__ float buf[8][8][16];     // [warp][head][k]
    for (int i = threadIdx.x; i < 16 * 128; i += blockDim.x) Wgs[i] = Wg[i];
    __syncthreads();
    int lane = threadIdx.x & 31, warp = threadIdx.x >> 5;
    int d = blockIdx.x * (blockDim.x >> 5) + warp;
    if (d >= Nn) return;
    int h = lane >> 2, j = lane & 3;
    float adh = g_ad[d * 8 + h];
    int r0 = g_row[d], r1 = g_row[d + 1];

    // init with self edge
    float m = leaky(g_as[d * 8 + h] + adh);
    float sum = 1.f;
    uint2 su = __ldg(&g_h3h[d * 4 + j]);
    float2 sf0 = __half22float2(*(const __half2*)&su.x);
    float2 sf1 = __half22float2(*(const __half2*)&su.y);
    float4 acc = make_float4(sf0.x, sf0.y, sf1.x, sf1.y);

    int k = r0;
    if (k + 3 < r1) {
        int i0 = __ldg(&g_csrc[k]), i1 = __ldg(&g_csrc[k + 1]);
        int i2 = __ldg(&g_csrc[k + 2]), i3 = __ldg(&g_csrc[k + 3]);
        while (true) {
            int kn = k + 4;
            bool more = (kn + 3 < r1);
            int n0, n1, n2, n3;
            if (more) {
                n0 = __ldg(&g_csrc[kn]);     n1 = __ldg(&g_csrc[kn + 1]);
                n2 = __ldg(&g_csrc[kn + 2]); n3 = __ldg(&g_csrc[kn + 3]);
            }
            float l0 = leaky(__ldg(&g_as[i0 * 8 + h]) + adh);
            float l1 = leaky(__ldg(&g_as[i1 * 8 + h]) + adh);
            float l2 = leaky(__ldg(&g_as[i2 * 8 + h]) + adh);
            float l3 = leaky(__ldg(&g_as[i3 * 8 + h]) + adh);
            uint2 u0 = __ldg(&g_h3h[i0 * 4 + j]);
            uint2 u1 = __ldg(&g_h3h[i1 * 4 + j]);
            uint2 u2 = __ldg(&g_h3h[i2 * 4 + j]);
            uint2 u3 = __ldg(&g_h3h[i3 * 4 + j]);
            gat_step(l0, u0, m, sum, acc);
            gat_step(l1, u1, m, sum, acc);
            gat_step(l2, u2, m, sum, acc);
            gat_step(l3, u3, m, sum, acc);
            k = kn;
            if (!more) break;
            i0 = n0; i1 = n1; i2 = n2; i3 = n3;
        }
    }
    for (; k < r1; k++) {
        int s = __ldg(&g_csrc[k]);
        float l = leaky(__ldg(&g_as[s * 8 + h]) + adh);
        gat_step(l, __ldg(&g_h3h[s * 4 + j]), m, sum, acc);
    }
    float sc = 0.125f / sum;  // alpha-normalize + head-mean
    buf[warp][h][j * 4 + 0] = acc.x * sc;
    buf[warp][h][j * 4 + 1] = acc.y * sc;
    buf[warp][h][j * 4 + 2] = acc.z * sc;
    buf[warp][h][j * 4 + 3] = acc.w * sc;
    __syncwarp();

    // mini-GEMM: hg[c] = bg[c] + sum_h sum_k buf[h][k]*Wg[k][h*16+c]; then pool
    if (lane < 4) {
        float4 hg = ((const float4*)bg)[lane];
#pragma unroll
        for (int hh = 0; hh < 8; hh++) {
#pragma unroll
            for (int kk = 0; kk < 16; kk++) {
                float a = buf[warp][hh][kk];
                const float4 w = *(const float4*)&Wgs[kk * 128 + hh * 16 + lane * 4];
                hg.x += a * w.x; hg.y += a * w.y; hg.z += a * w.z; hg.w += a * w.w;
            }
        }
        red4(((float4*)g_pool) + batch[d] * 4 + lane, hg);
    }
}

__global__ void k_final(const float* __restrict__ Wf, const float* __restrict__ bf,
                        float* __restrict__ out) {
    int i = blockIdx.x * blockDim.x + threadIdx.x;
    if (i >= Gg * 3) return;
    int gg = i / 3, k = i % 3;
    float s = bf[k];
#pragma unroll
    for (int c = 0; c < 16; c++) s += g_pool[gg * 16 + c] * Wf[c * 3 + k];
    out[i] = s;
}

// ---------------- launch ----------------
static inline void* symaddr(const void* s) { void* p = nullptr; cudaGetSymbolAddress(&p, s); return p; }

extern "C" void kernel_launch(void* const* d_in, const int* in_sizes, int n_in,
                              void* d_out, int out_size) {
    const float* x       = (const float*)d_in[0];
    const int*   ei      = (const int*)  d_in[1];
    const int*   batch   = (const int*)  d_in[2];
    const float* W1 = (const float*)d_in[3],  *b1 = (const float*)d_in[4];
    const float* g1 = (const float*)d_in[5],  *be1= (const float*)d_in[6];
    const float* W2 = (const float*)d_in[7],  *b2 = (const float*)d_in[8];
    const float* g2 = (const float*)d_in[9],  *be2= (const float*)d_in[10];
    const float* W3 = (const float*)d_in[11], *b3 = (const float*)d_in[12];
    const float* g3 = (const float*)d_in[13], *be3= (const float*)d_in[14];
    const float* Wg = (const float*)d_in[15];
    const float* att_src = (const float*)d_in[16];
    const float* att_dst = (const float*)d_in[17];
    const float* bg = (const float*)d_in[18];
    const float* Wf = (const float*)d_in[19], *bf = (const float*)d_in[20];
    float* out = (float*)d_out;
    const int E = in_sizes[1] / 2;

    float* axp  = (float*)symaddr(g_axp);
    float* acc1 = (float*)symaddr(g_acc1);
    float* acc2 = (float*)symaddr(g_acc2);
    float* acc3 = (float*)symaddr(g_acc3);
    float* bn   = (float*)symaddr(g_bn);
    uint4* xh   = (uint4*)symaddr(g_xh);
    uint4* t2h  = (uint4*)symaddr(g_t2h);
    uint4* t3h  = (uint4*)symaddr(g_t3h);

    const int B = 256;
    // ---- CSR build ----
    k_init<<<(Nn + B - 1) / B, B>>>();
    k_deg<<<(E / 4 + B) / B, B>>>(ei, E);
    k_scan<<<1, 1024>>>();
    k_fill<<<(E / 4 + B) / B, B>>>(ei, E);
    k_convx<<<(Nn * 32 + B - 1) / B, B>>>(x);

    // ---- GCN layer 1: aggregate x' (half), GEMM 20->64 (+stats) ----
    k_gcn<4, false><<<(Nn + 63) / 64, B>>>(xh, nullptr, (float4*)axp, nullptr);
    k_gemm1<<<Nn / 8, 512>>>(axp, W1, b1, acc1, bn + 0);

    // ---- GCN layer 2: fused BN1+ReLU+GEMM 64->32 (*dinv, half), aggregate (+stats) ----
    k_gemmbn<64, 32><<<Nn / 16, 512>>>(acc1, bn + 0, g1, be1, W2, (__half*)t2h);
    k_gcn<4, true><<<(Nn + 63) / 64, B>>>(t2h, b2, (float4*)acc2, bn + 128);

    // ---- GCN layer 3: fused BN2+ReLU+GEMM 32->16 (*dinv, half), aggregate (+stats) ----
    k_gemmbn<32, 16><<<Nn / 32, 512>>>(acc2, bn + 128, g2, be2, W3, (__half*)t3h);
    k_gcn<2, true><<<(Nn + 127) / 128, B>>>(t3h, b3, (float4*)acc3, bn + 256);

    // ---- BN3 + attention dots fused, then single-pass GAT ----
    k_prep<<<1, 128>>>(Wg, att_src, att_dst);
    k_bn3att<<<Nn / 16, B>>>(acc3, bn + 256, g3, be3);
    k_gat<<<(Nn + 7) / 8, B>>>(Wg, bg, batch);

    // ---- classifier ----
    k_final<<<(Gg * 3 + B - 1) / B, B>>>(Wf, bf, out);
}